// round 16
// baseline (speedup 1.0000x reference)
#include <cuda_runtime.h>
#include <cuda_bf16.h>
#include <cuda_fp16.h>
#include <cstdint>
#include <math.h>

// Problem constants
#define B_  2
#define S_  2048
#define HID 2048
#define NH  16
#define HD  128
#define HALF 64
#define ROWS (B_ * S_)            // 4096
#define QKV_W (3 * HID)           // 6144
#define EPS 1e-5f
#define SCALE 0.08838834764831845f   // 1/sqrt(128)
#define LOG2E 1.4426950408889634f

// Scratch (device-global; no runtime allocation allowed)
__device__ __half g_qkvh[(size_t)ROWS * QKV_W];          // gemm1 out (fp16)
__device__ float g_cos[S_ * HALF];
__device__ float g_sin[S_ * HALF];
__device__ __half g_a_hi[(size_t)ROWS * HID];            // gemm A plane (x; then O)
__device__ __half g_b1[(size_t)QKV_W * HID];             // w_in plane
__device__ __half g_b2[(size_t)HID * HID];               // w_out plane
__device__ __half g_q_hi[(size_t)ROWS * HID];            // Q plane (log2e/sqrt(HD) folded)
__device__ __half g_k_hi[(size_t)ROWS * HID];

__device__ __forceinline__ uint32_t smem_u32(const void* p) {
    uint32_t a;
    asm("{ .reg .u64 t; cvta.to.shared.u64 t, %1; cvt.u32.u64 %0, t; }" : "=r"(a) : "l"(p));
    return a;
}
#define SWZ(x) ((x) ^ (((x) >> 3) & 0x70))

__device__ __forceinline__ void ldsm_x4(uint32_t* r, uint32_t addr) {
    asm volatile("ldmatrix.sync.aligned.m8n8.x4.shared.b16 {%0,%1,%2,%3}, [%4];"
                 : "=r"(r[0]), "=r"(r[1]), "=r"(r[2]), "=r"(r[3]) : "r"(addr));
}
__device__ __forceinline__ void ldsm_x4_t(uint32_t* r, uint32_t addr) {
    asm volatile("ldmatrix.sync.aligned.m8n8.x4.trans.shared.b16 {%0,%1,%2,%3}, [%4];"
                 : "=r"(r[0]), "=r"(r[1]), "=r"(r[2]), "=r"(r[3]) : "r"(addr));
}
// fp16 in, f32 acc
__device__ __forceinline__ void mma_f16f32(float* c, const uint32_t* a,
                                           uint32_t b0, uint32_t b1) {
    asm volatile(
        "mma.sync.aligned.m16n8k16.row.col.f32.f16.f16.f32 "
        "{%0,%1,%2,%3}, {%4,%5,%6,%7}, {%8,%9}, {%0,%1,%2,%3};"
        : "+f"(c[0]), "+f"(c[1]), "+f"(c[2]), "+f"(c[3])
        : "r"(a[0]), "r"(a[1]), "r"(a[2]), "r"(a[3]), "r"(b0), "r"(b1));
}
__device__ __forceinline__ uint32_t pack_h2(float lo, float hi) {
    __half2 h = __floats2half2_rn(lo, hi);
    return *(uint32_t*)&h;
}

// ---------------------------------------------------------------------------
// RoPE table
// ---------------------------------------------------------------------------
__global__ void rope_table_kernel() {
    int idx = blockIdx.x * blockDim.x + threadIdx.x;
    if (idx >= S_ * HALF) return;
    int s = idx >> 6;
    int j = idx & 63;
    float freq = powf(10000.0f, -(float)j * (1.0f / 64.0f));
    float sn, cs;
    sincosf((float)s * freq, &sn, &cs);
    g_cos[idx] = cs;
    g_sin[idx] = sn;
}

// ---------------------------------------------------------------------------
// Fused fp32 -> fp16 round for x, w_in, w_out in one launch
// ---------------------------------------------------------------------------
#define N1F4 (ROWS * HID / 4)
#define N2F4 (QKV_W * HID / 4)
#define N3F4 (HID * HID / 4)
__global__ void __launch_bounds__(256) tohalf3_kernel(
    const float* __restrict__ x, __half* __restrict__ dx,
    const float* __restrict__ w1, __half* __restrict__ dw1,
    const float* __restrict__ w2, __half* __restrict__ dw2)
{
    int i = blockIdx.x * blockDim.x + threadIdx.x;
    const float* src;
    __half* dst;
    int off;
    if (i < N1F4)                { src = x;  dst = dx;  off = i; }
    else if (i < N1F4 + N2F4)    { src = w1; dst = dw1; off = i - N1F4; }
    else if (i < N1F4 + N2F4 + N3F4) { src = w2; dst = dw2; off = i - N1F4 - N2F4; }
    else return;
    float4 v = ((const float4*)src)[off];
    uint64_t hp = 0;
    hp |= (uint64_t)__half_as_ushort(__float2half_rn(v.x));
    hp |= (uint64_t)__half_as_ushort(__float2half_rn(v.y)) << 16;
    hp |= (uint64_t)__half_as_ushort(__float2half_rn(v.z)) << 32;
    hp |= (uint64_t)__half_as_ushort(__float2half_rn(v.w)) << 48;
    *(uint64_t*)(dst + (size_t)off * 4) = hp;
}

// ---------------------------------------------------------------------------
// 1-term fp16 GEMM (f32 acc):  C = A*B^T.  H16OUT selects fp16/fp32 output.
// ---------------------------------------------------------------------------
template<int MT, int NP, int NSTG, bool H16OUT>
__global__ void __launch_bounds__(512, 1) gemm_t(
    const __half* __restrict__ A, const __half* __restrict__ B,
    void* __restrict__ Cv, int M, int N, int tiles_m)
{
    constexpr int BM = MT * 64;
    constexpr int BN = NP * 64;
    constexpr int A_PLANE = BM * 128;
    constexpr int B_PLANE = BN * 128;
    constexpr int SA = 0, SB = A_PLANE;
    constexpr int STG = A_PLANE + B_PLANE;
    constexpr int ACH = BM * 8;
    constexpr int BCH = BN * 8;
    constexpr int NLD = (ACH + BCH) / 512;
    static_assert((ACH + BCH) % 512 == 0, "loader divisibility");
    constexpr int NKT = HID / 64;

    extern __shared__ char smem[];
    const uint32_t sb = smem_u32(smem);
    const int tid = threadIdx.x;
    const int wid = tid >> 5, lid = tid & 31;
    const int m0 = (blockIdx.x % tiles_m) * BM;
    const int n0 = (blockIdx.x / tiles_m) * BN;
    const int wm = (wid & 3) * (MT * 16);
    const int wn = (wid >> 2) * (NP * 16);
    const int lrow = lid & 15;
    const int lhi = (lid >> 4) * 16;

    auto load_stage = [&](int st, int kt) {
        uint32_t sbase = sb + st * STG;
#pragma unroll
        for (int u = 0; u < NLD; u++) {
            int c = tid + u * 512;
            const __half* gp;
            uint32_t dst;
            if (c < ACH) {
                int r = c >> 3, c16 = c & 7;
                gp = A + (size_t)(m0 + r) * HID + kt * 64 + c16 * 8;
                dst = sbase + SA + SWZ(r * 128 + c16 * 16);
            } else {
                int cc = c - ACH;
                int r = cc >> 3, c16 = cc & 7;
                gp = B + (size_t)(n0 + r) * HID + kt * 64 + c16 * 8;
                dst = sbase + SB + SWZ(r * 128 + c16 * 16);
            }
            asm volatile("cp.async.cg.shared.global [%0], [%1], 16;"
                         :: "r"(dst), "l"(gp) : "memory");
        }
    };

#pragma unroll
    for (int s = 0; s < NSTG - 1; s++) {
        load_stage(s, s);
        asm volatile("cp.async.commit_group;" ::: "memory");
    }

    float acc[MT][NP * 2][4];
#pragma unroll
    for (int mt = 0; mt < MT; mt++)
#pragma unroll
        for (int nt = 0; nt < NP * 2; nt++)
#pragma unroll
            for (int q = 0; q < 4; q++) acc[mt][nt][q] = 0.0f;

    for (int kt = 0; kt < NKT; kt++) {
        if (kt + NSTG - 1 < NKT) load_stage((kt + NSTG - 1) % NSTG, kt + NSTG - 1);
        asm volatile("cp.async.commit_group;" ::: "memory");
        asm volatile("cp.async.wait_group %0;" :: "n"(NSTG - 1) : "memory");
        __syncthreads();

        const uint32_t sbase = sb + (kt % NSTG) * STG;

#pragma unroll
        for (int ks = 0; ks < 4; ks++) {
            const int cb = ks * 32 + lhi;
            uint32_t af[MT][4];
#pragma unroll
            for (int mt = 0; mt < MT; mt++) {
                int row = wm + mt * 16 + lrow;
                ldsm_x4(af[mt], sbase + SA + row * 128 + (cb ^ ((row & 7) * 16)));
            }
#pragma unroll
            for (int np = 0; np < NP; np++) {
                int brow = wn + np * 16 + lrow;
                uint32_t bh4[4];
                ldsm_x4(bh4, sbase + SB + brow * 128 + (cb ^ ((brow & 7) * 16)));
#pragma unroll
                for (int mt = 0; mt < MT; mt++) {
                    mma_f16f32(acc[mt][np * 2 + 0], af[mt], bh4[0], bh4[2]);
                    mma_f16f32(acc[mt][np * 2 + 1], af[mt], bh4[1], bh4[3]);
                }
            }
        }
        __syncthreads();
    }

    const int er = m0 + wm + (lid >> 2);
    const int ec = n0 + wn + (lid & 3) * 2;
#pragma unroll
    for (int mt = 0; mt < MT; mt++)
#pragma unroll
        for (int nt = 0; nt < NP * 2; nt++) {
            if (H16OUT) {
                __half* Ch = (__half*)Cv;
                *(uint32_t*)(Ch + (size_t)(er + mt * 16) * N + ec + nt * 8) =
                    pack_h2(acc[mt][nt][0], acc[mt][nt][1]);
                *(uint32_t*)(Ch + (size_t)(er + mt * 16 + 8) * N + ec + nt * 8) =
                    pack_h2(acc[mt][nt][2], acc[mt][nt][3]);
            } else {
                float* C = (float*)Cv;
                float* c0 = C + (size_t)(er + mt * 16) * N + ec + nt * 8;
                *(float2*)c0 = make_float2(acc[mt][nt][0], acc[mt][nt][1]);
                float* c1 = c0 + 8 * N;
                *(float2*)c1 = make_float2(acc[mt][nt][2], acc[mt][nt][3]);
            }
        }
}

#define GEMM1_SMEM (4 * (128 * 128 + 192 * 128))   // 163840
#define GEMM2_SMEM (4 * (64 * 128 + 128 * 128))    // 98304

// ---------------------------------------------------------------------------
// Fused qk RMSNorm + RoPE on fp16 QKV: Q,K -> single fp16 planes.
// Q scaled by log2e/sqrt(HD).
// ---------------------------------------------------------------------------
__global__ void __launch_bounds__(256) normrope_kernel(
    const __half* __restrict__ qkvh,
    const float* __restrict__ nw_q, const float* __restrict__ nw_k,
    __half* __restrict__ qh, __half* __restrict__ kh)
{
    __shared__ float buf[HID];
    __shared__ float warpred[8];

    const int row = blockIdx.x;
    const int s = row & (S_ - 1);
    const int tid = threadIdx.x;

#pragma unroll
    for (int part = 0; part < 2; part++) {
        const __half* src = qkvh + (size_t)row * QKV_W + part * HID;
        const float* w = (part == 0) ? nw_q : nw_k;
        __half* dst = (part == 0) ? qh : kh;

        float ss = 0.0f;
        {
            uint4 v = *(const uint4*)(src + tid * 8);
            const __half2* hp = (const __half2*)&v;
#pragma unroll
            for (int q = 0; q < 4; q++) {
                float2 f = __half22float2(hp[q]);
                buf[tid * 8 + q * 2]     = f.x;
                buf[tid * 8 + q * 2 + 1] = f.y;
                ss += f.x * f.x + f.y * f.y;
            }
        }
#pragma unroll
        for (int o = 16; o; o >>= 1) ss += __shfl_xor_sync(0xffffffffu, ss, o);
        if ((tid & 31) == 0) warpred[tid >> 5] = ss;
        __syncthreads();
        float tot = 0.0f;
#pragma unroll
        for (int wi = 0; wi < 8; wi++) tot += warpred[wi];
        float rn = rsqrtf(tot * (1.0f / (float)HID) + EPS);
        if (part == 0) rn *= SCALE * LOG2E;

#pragma unroll
        for (int u = 0; u < 4; u++) {
            int p = tid + u * 256;
            int hh = p >> 6;
            int j = p & 63;
            int i1 = hh * HD + j;
            int i2 = i1 + HALF;
            float x1 = buf[i1] * rn * w[i1];
            float x2 = buf[i2] * rn * w[i2];
            float cs = g_cos[s * HALF + j];
            float sn = g_sin[s * HALF + j];
            size_t base = (size_t)row * HID;
            dst[base + i1] = __float2half_rn(x1 * cs - x2 * sn);
            dst[base + i2] = __float2half_rn(x2 * cs + x1 * sn);
        }
        __syncthreads();
    }
}

// ---------------------------------------------------------------------------
// Flash attention, fp16 mma.sync: QK 1-term, PV 1-term, base-2 softmax.
// V staged from fp16 QKV rows; PV B-frags via ldmatrix.trans.
// 64 q rows x (b,h), 128 threads / 4 warps.
// 3-stage KV ring, ONE barrier per ktile. smem 112KB -> 2 CTAs/SM (224<=228).
// ---------------------------------------------------------------------------
#define SQ 0
#define KVSTG 32768
#define SK(s) (16384 + (s) * KVSTG)
#define SV(s) (SK(s) + 16384)
#define ATTN_SMEM (16384 + 3 * KVSTG)   // 114688

__global__ void __launch_bounds__(128) attn_mma(
    const __half* __restrict__ qh, const __half* __restrict__ kh,
    const __half* __restrict__ qkvh, __half* __restrict__ ohi)
{
    extern __shared__ char smem[];
    const uint32_t sb = smem_u32(smem);
    const int tid = threadIdx.x;
    const int wid = tid >> 5, lid = tid & 31;
    const int lrow = lid & 15;
    const int lhi = (lid >> 4) * 16;
    const int bh = blockIdx.y;
    const int b = bh >> 4, h = bh & 15;
    const int qt = gridDim.x - 1 - blockIdx.x;   // heavy tiles first
    const int q0 = qt * 64;
    const int nkb = qt + 1;
    const int wm = wid * 16;

    // trans-load lane geometry for V fragments
    const int vm = lid >> 3;
    const int vrow_l = (vm & 1) * 8 + (lid & 7);
    const int vcol_l = (vm >> 1) * 8;

    // ---- load Q (64 rows): group 0 ----
#pragma unroll
    for (int u = 0; u < 8; u++) {
        int c = tid + u * 128;
        int r = c >> 4, ch = c & 15;
        int p = ch >> 3, c8 = ch & 7;
        const __half* src = qh + ((size_t)(b * 2048 + q0 + r) * HID + h * HD + ch * 8);
        uint32_t dst = sb + SQ + p * 8192 + SWZ(r * 128 + c8 * 16);
        asm volatile("cp.async.cg.shared.global [%0], [%1], 16;"
                     :: "r"(dst), "l"(src) : "memory");
    }
    asm volatile("cp.async.commit_group;" ::: "memory");

// 2048 16B-chunks per stage: K (1024 from kh) + V (1024 from qkvh rows)
#define LOAD_KV(s, kt) do {                                                    \
    int k0 = (kt) * 64;                                                        \
    _Pragma("unroll")                                                          \
    for (int u = 0; u < 16; u++) {                                             \
        int c = tid + u * 128;                                                 \
        if (c < 1024) {                                                        \
            int r = c >> 4, ch = c & 15;                                       \
            int p = ch >> 3, c8 = ch & 7;                                      \
            const __half* src = kh +                                           \
                ((size_t)(b * 2048 + k0 + r) * HID + h * HD + ch * 8);         \
            uint32_t dst = sb + SK(s) + p * 8192 + SWZ(r * 128 + c8 * 16);     \
            asm volatile("cp.async.cg.shared.global [%0], [%1], 16;"           \
                         :: "r"(dst), "l"(src) : "memory");                    \
        } else {                                                               \
            int cc = c - 1024;                                                 \
            int r = cc >> 4, ch = cc & 15;                                     \
            int p = ch >> 3, c8 = ch & 7;                                      \
            const __half* src = qkvh +                                         \
                ((size_t)(b * 2048 + k0 + r) * QKV_W + 2 * HID + h * HD + ch * 8); \
            uint32_t dst = sb + SV(s) + p * 8192 + SWZ(r * 128 + c8 * 16);     \
            asm volatile("cp.async.cg.shared.global [%0], [%1], 16;"           \
                         :: "r"(dst), "l"(src) : "memory");                    \
        }                                                                      \
    }                                                                          \
} while (0)

    // prologue: stages 0 and 1 (groups 1, 2)
    LOAD_KV(0, 0);
    asm volatile("cp.async.commit_group;" ::: "memory");
    if (nkb > 1) LOAD_KV(1, 1);
    asm volatile("cp.async.commit_group;" ::: "memory");

    // ---- Q ready (allow both KV groups pending), hoist Q fragments ----
    asm volatile("cp.async.wait_group 2;" ::: "memory");
    __syncthreads();
    uint32_t qr[8][4];
#pragma unroll
    for (int kk = 0; kk < 8; kk++) {
        int p = kk >> 2;
        int cb = (kk & 3) * 32 + lhi;
        int arow = wm + lrow;
        ldsm_x4(qr[kk], sb + SQ + p * 8192 + arow * 128 + (cb ^ ((arow & 7) * 16)));
    }

    float accO[16][4];
#pragma unroll
    for (int nt = 0; nt < 16; nt++)
#pragma unroll
        for (int q = 0; q < 4; q++) accO[nt][q] = 0.0f;
    float m0v = -1e30f, m1v = -1e30f, l0v = 0.0f, l1v = 0.0f;

    const int grow0 = q0 + wm + (lid >> 2);
    const int grow1 = grow0 + 8;

    for (int kt = 0; kt < nkb; kt++) {
        // KV(kt) complete (<=1 group pending: KV(kt+1))
        asm volatile("cp.async.wait_group 1;" ::: "memory");
        __syncthreads();   // single barrier: data visible + all warps past kt-1

        // prefetch kt+2 into the stage freed at kt-1
        if (kt + 2 < nkb) LOAD_KV((kt + 2) % 3, kt + 2);
        asm volatile("cp.async.commit_group;" ::: "memory");

        // fully-masked ktile for this warp?
        if (kt * 64 > q0 + wm + 15) continue;

        const int s = kt % 3;

        // ---- S = Q*K  (logits in log2 units) ----
        float sa[8][4];
#pragma unroll
        for (int nt = 0; nt < 8; nt++)
#pragma unroll
            for (int q = 0; q < 4; q++) sa[nt][q] = 0.0f;

#pragma unroll
        for (int kk = 0; kk < 8; kk++) {
            int p = kk >> 2;
            int cb = (kk & 3) * 32 + lhi;
#pragma unroll
            for (int np = 0; np < 4; np++) {
                int brow = np * 16 + lrow;
                uint32_t boff = p * 8192 + brow * 128 + (cb ^ ((brow & 7) * 16));
                uint32_t khf[4];
                ldsm_x4(khf, sb + SK(s) + boff);
                mma_f16f32(sa[np * 2 + 0], qr[kk], khf[0], khf[2]);
                mma_f16f32(sa[np * 2 + 1], qr[kk], khf[1], khf[3]);
            }
        }

        // ---- causal mask ----
        if ((kt + 1) * 64 - 1 > q0 + wm) {
            const int colb = kt * 64 + (lid & 3) * 2;
#pragma unroll
            for (int nt = 0; nt < 8; nt++) {
                int col = colb + nt * 8;
                if (col > grow0)     sa[nt][0] = -1e30f;
                if (col + 1 > grow0) sa[nt][1] = -1e30f;
                if (col > grow1)     sa[nt][2] = -1e30f;
                if (col + 1 > grow1) sa[nt][3] = -1e30f;
            }
        }

        // ---- online softmax (base 2) ----
        float mx0 = m0v, mx1 = m1v;
#pragma unroll
        for (int nt = 0; nt < 8; nt++) {
            mx0 = fmaxf(mx0, fmaxf(sa[nt][0], sa[nt][1]));
            mx1 = fmaxf(mx1, fmaxf(sa[nt][2], sa[nt][3]));
        }
        mx0 = fmaxf(mx0, __shfl_xor_sync(0xffffffffu, mx0, 1));
        mx0 = fmaxf(mx0, __shfl_xor_sync(0xffffffffu, mx0, 2));
        mx1 = fmaxf(mx1, __shfl_xor_sync(0xffffffffu, mx1, 1));
        mx1 = fmaxf(mx1, __shfl_xor_sync(0xffffffffu, mx1, 2));
        float alpha0 = exp2f(m0v - mx0);
        float alpha1 = exp2f(m1v - mx1);
        m0v = mx0; m1v = mx1;

        float ls0 = 0.0f, ls1 = 0.0f;
#pragma unroll
        for (int nt = 0; nt < 8; nt++) {
            sa[nt][0] = exp2f(sa[nt][0] - mx0);
            sa[nt][1] = exp2f(sa[nt][1] - mx0);
            sa[nt][2] = exp2f(sa[nt][2] - mx1);
            sa[nt][3] = exp2f(sa[nt][3] - mx1);
            ls0 += sa[nt][0] + sa[nt][1];
            ls1 += sa[nt][2] + sa[nt][3];
        }
        ls0 += __shfl_xor_sync(0xffffffffu, ls0, 1);
        ls0 += __shfl_xor_sync(0xffffffffu, ls0, 2);
        ls1 += __shfl_xor_sync(0xffffffffu, ls1, 1);
        ls1 += __shfl_xor_sync(0xffffffffu, ls1, 2);
        l0v = l0v * alpha0 + ls0;
        l1v = l1v * alpha1 + ls1;

#pragma unroll
        for (int nt = 0; nt < 16; nt++) {
            accO[nt][0] *= alpha0; accO[nt][1] *= alpha0;
            accO[nt][2] *= alpha1; accO[nt][3] *= alpha1;
        }

        // ---- P -> fp16 A-fragments ----
        uint32_t phA[8], phB[8];
#pragma unroll
        for (int nt = 0; nt < 8; nt++) {
            phA[nt] = pack_h2(sa[nt][0], sa[nt][1]);
            phB[nt] = pack_h2(sa[nt][2], sa[nt][3]);
        }

        // ---- O += P*V  (V frags via ldmatrix.trans from [token][d]) ----
#pragma unroll
        for (int ki = 0; ki < 4; ki++) {
            uint32_t aH[4] = {phA[2 * ki], phB[2 * ki], phA[2 * ki + 1], phB[2 * ki + 1]};
            int token = ki * 16 + vrow_l;
#pragma unroll
            for (int np = 0; np < 8; np++) {
                int dcol = np * 16 + vcol_l;
                int p = dcol >> 6;
                int colb = (dcol & 63) * 2;
                uint32_t vhf[4];
                ldsm_x4_t(vhf, sb + SV(s) + p * 8192 + token * 128 +
                               (colb ^ ((token & 7) * 16)));
                mma_f16f32(accO[np * 2 + 0], aH, vhf[0], vhf[1]);
                mma_f16f32(accO[np * 2 + 1], aH, vhf[2], vhf[3]);
            }
        }
    }

    // ---- epilogue: O/l -> single fp16 plane ----
    float inv0 = 1.0f / l0v, inv1 = 1.0f / l1v;
#pragma unroll
    for (int nt = 0; nt < 16; nt++) {
        int col = h * HD + nt * 8 + (lid & 3) * 2;
        size_t r0 = (size_t)(b * 2048 + grow0) * HID + col;
        size_t r1 = (size_t)(b * 2048 + grow1) * HID + col;
        *(uint32_t*)(ohi + r0) = pack_h2(accO[nt][0] * inv0, accO[nt][1] * inv0);
        *(uint32_t*)(ohi + r1) = pack_h2(accO[nt][2] * inv1, accO[nt][3] * inv1);
    }
#undef LOAD_KV
}

// ---------------------------------------------------------------------------
// launch
// ---------------------------------------------------------------------------
extern "C" void kernel_launch(void* const* d_in, const int* in_sizes, int n_in,
                              void* d_out, int out_size)
{
    const float* x     = (const float*)d_in[0];
    const float* w_in  = (const float*)d_in[1];
    const float* w_out = (const float*)d_in[2];
    const float* qnw   = (const float*)d_in[3];
    const float* knw   = (const float*)d_in[4];
    float* out = (float*)d_out;

    __half *qkvh, *ah, *b1, *b2, *qh, *kh;
    cudaGetSymbolAddress((void**)&qkvh, g_qkvh);
    cudaGetSymbolAddress((void**)&ah, g_a_hi);
    cudaGetSymbolAddress((void**)&b1, g_b1);
    cudaGetSymbolAddress((void**)&b2, g_b2);
    cudaGetSymbolAddress((void**)&qh, g_q_hi);
    cudaGetSymbolAddress((void**)&kh, g_k_hi);

    cudaFuncSetAttribute(gemm_t<2, 3, 4, true>, cudaFuncAttributeMaxDynamicSharedMemorySize, GEMM1_SMEM);
    cudaFuncSetAttribute(gemm_t<1, 2, 4, false>, cudaFuncAttributeMaxDynamicSharedMemorySize, GEMM2_SMEM);
    cudaFuncSetAttribute(attn_mma, cudaFuncAttributeMaxDynamicSharedMemorySize, ATTN_SMEM);

    // 1. one pass: x -> a plane, w_in -> b1, w_out -> b2 (fp16); rope table
    tohalf3_kernel<<<(N1F4 + N2F4 + N3F4 + 255) / 256, 256>>>(x, ah, w_in, b1, w_out, b2);
    rope_table_kernel<<<(S_ * HALF + 255) / 256, 256>>>();

    // 2. QKV = x @ w_in^T -> fp16 (128x192 tiles, 1024 CTAs)
    gemm_t<2, 3, 4, true><<<(ROWS / 128) * (QKV_W / 192), 512, GEMM1_SMEM>>>(
        ah, b1, qkvh, ROWS, QKV_W, ROWS / 128);

    // 3. norm/rope on fp16 QKV (Q pre-scaled by log2e)
    normrope_kernel<<<ROWS, 256>>>(qkvh, qnw, knw, qh, kh);

    // 4. attention (3-stage single-barrier pipeline) -> fp16 O plane in ah
    attn_mma<<<dim3(S_ / 64, B_ * NH), 128, ATTN_SMEM>>>(qh, kh, qkvh, ah);

    // 5. out = O @ w_out^T (fp32 out)
    gemm_t<1, 2, 4, false><<<(ROWS / 64) * (HID / 128), 512, GEMM2_SMEM>>>(
        ah, b2, out, ROWS, HID, ROWS / 64);
}

// round 17
// speedup vs baseline: 1.0229x; 1.0229x over previous
#include <cuda_runtime.h>
#include <cuda_bf16.h>
#include <cuda_fp16.h>
#include <cstdint>
#include <math.h>

// Problem constants
#define B_  2
#define S_  2048
#define HID 2048
#define NH  16
#define HD  128
#define HALF 64
#define ROWS (B_ * S_)            // 4096
#define QKV_W (3 * HID)           // 6144
#define EPS 1e-5f
#define SCALE 0.08838834764831845f   // 1/sqrt(128)
#define LOG2E 1.4426950408889634f

// Scratch (device-global; no runtime allocation allowed)
__device__ __half g_qkvh[(size_t)ROWS * QKV_W];          // gemm1 out (fp16)
__device__ float g_cos[S_ * HALF];
__device__ float g_sin[S_ * HALF];
__device__ __half g_a_hi[(size_t)ROWS * HID];            // gemm A plane (x; then O)
__device__ __half g_b1[(size_t)QKV_W * HID];             // w_in plane
__device__ __half g_b2[(size_t)HID * HID];               // w_out plane
__device__ __half g_q_hi[(size_t)ROWS * HID];            // Q plane (log2e/sqrt(HD) folded)
__device__ __half g_k_hi[(size_t)ROWS * HID];

__device__ __forceinline__ uint32_t smem_u32(const void* p) {
    uint32_t a;
    asm("{ .reg .u64 t; cvta.to.shared.u64 t, %1; cvt.u32.u64 %0, t; }" : "=r"(a) : "l"(p));
    return a;
}
#define SWZ(x) ((x) ^ (((x) >> 3) & 0x70))

__device__ __forceinline__ void ldsm_x4(uint32_t* r, uint32_t addr) {
    asm volatile("ldmatrix.sync.aligned.m8n8.x4.shared.b16 {%0,%1,%2,%3}, [%4];"
                 : "=r"(r[0]), "=r"(r[1]), "=r"(r[2]), "=r"(r[3]) : "r"(addr));
}
__device__ __forceinline__ void ldsm_x4_t(uint32_t* r, uint32_t addr) {
    asm volatile("ldmatrix.sync.aligned.m8n8.x4.trans.shared.b16 {%0,%1,%2,%3}, [%4];"
                 : "=r"(r[0]), "=r"(r[1]), "=r"(r[2]), "=r"(r[3]) : "r"(addr));
}
// fp16 in, f32 acc
__device__ __forceinline__ void mma_f16f32(float* c, const uint32_t* a,
                                           uint32_t b0, uint32_t b1) {
    asm volatile(
        "mma.sync.aligned.m16n8k16.row.col.f32.f16.f16.f32 "
        "{%0,%1,%2,%3}, {%4,%5,%6,%7}, {%8,%9}, {%0,%1,%2,%3};"
        : "+f"(c[0]), "+f"(c[1]), "+f"(c[2]), "+f"(c[3])
        : "r"(a[0]), "r"(a[1]), "r"(a[2]), "r"(a[3]), "r"(b0), "r"(b1));
}
__device__ __forceinline__ uint32_t pack_h2(float lo, float hi) {
    __half2 h = __floats2half2_rn(lo, hi);
    return *(uint32_t*)&h;
}

// ---------------------------------------------------------------------------
// RoPE table
// ---------------------------------------------------------------------------
__global__ void rope_table_kernel() {
    int idx = blockIdx.x * blockDim.x + threadIdx.x;
    if (idx >= S_ * HALF) return;
    int s = idx >> 6;
    int j = idx & 63;
    float freq = powf(10000.0f, -(float)j * (1.0f / 64.0f));
    float sn, cs;
    sincosf((float)s * freq, &sn, &cs);
    g_cos[idx] = cs;
    g_sin[idx] = sn;
}

// ---------------------------------------------------------------------------
// Fused fp32 -> fp16 round for x, w_in, w_out in one launch
// ---------------------------------------------------------------------------
#define N1F4 (ROWS * HID / 4)
#define N2F4 (QKV_W * HID / 4)
#define N3F4 (HID * HID / 4)
__global__ void __launch_bounds__(256) tohalf3_kernel(
    const float* __restrict__ x, __half* __restrict__ dx,
    const float* __restrict__ w1, __half* __restrict__ dw1,
    const float* __restrict__ w2, __half* __restrict__ dw2)
{
    int i = blockIdx.x * blockDim.x + threadIdx.x;
    const float* src;
    __half* dst;
    int off;
    if (i < N1F4)                { src = x;  dst = dx;  off = i; }
    else if (i < N1F4 + N2F4)    { src = w1; dst = dw1; off = i - N1F4; }
    else if (i < N1F4 + N2F4 + N3F4) { src = w2; dst = dw2; off = i - N1F4 - N2F4; }
    else return;
    float4 v = ((const float4*)src)[off];
    uint64_t hp = 0;
    hp |= (uint64_t)__half_as_ushort(__float2half_rn(v.x));
    hp |= (uint64_t)__half_as_ushort(__float2half_rn(v.y)) << 16;
    hp |= (uint64_t)__half_as_ushort(__float2half_rn(v.z)) << 32;
    hp |= (uint64_t)__half_as_ushort(__float2half_rn(v.w)) << 48;
    *(uint64_t*)(dst + (size_t)off * 4) = hp;
}

// ---------------------------------------------------------------------------
// 1-term fp16 GEMM (f32 acc):  C = A*B^T.  H16OUT selects fp16/fp32 output.
// ---------------------------------------------------------------------------
template<int MT, int NP, int NSTG, bool H16OUT>
__global__ void __launch_bounds__(512, 1) gemm_t(
    const __half* __restrict__ A, const __half* __restrict__ B,
    void* __restrict__ Cv, int M, int N, int tiles_m)
{
    constexpr int BM = MT * 64;
    constexpr int BN = NP * 64;
    constexpr int A_PLANE = BM * 128;
    constexpr int B_PLANE = BN * 128;
    constexpr int SA = 0, SB = A_PLANE;
    constexpr int STG = A_PLANE + B_PLANE;
    constexpr int ACH = BM * 8;
    constexpr int BCH = BN * 8;
    constexpr int NLD = (ACH + BCH) / 512;
    static_assert((ACH + BCH) % 512 == 0, "loader divisibility");
    constexpr int NKT = HID / 64;

    extern __shared__ char smem[];
    const uint32_t sb = smem_u32(smem);
    const int tid = threadIdx.x;
    const int wid = tid >> 5, lid = tid & 31;
    const int m0 = (blockIdx.x % tiles_m) * BM;
    const int n0 = (blockIdx.x / tiles_m) * BN;
    const int wm = (wid & 3) * (MT * 16);
    const int wn = (wid >> 2) * (NP * 16);
    const int lrow = lid & 15;
    const int lhi = (lid >> 4) * 16;

    auto load_stage = [&](int st, int kt) {
        uint32_t sbase = sb + st * STG;
#pragma unroll
        for (int u = 0; u < NLD; u++) {
            int c = tid + u * 512;
            const __half* gp;
            uint32_t dst;
            if (c < ACH) {
                int r = c >> 3, c16 = c & 7;
                gp = A + (size_t)(m0 + r) * HID + kt * 64 + c16 * 8;
                dst = sbase + SA + SWZ(r * 128 + c16 * 16);
            } else {
                int cc = c - ACH;
                int r = cc >> 3, c16 = cc & 7;
                gp = B + (size_t)(n0 + r) * HID + kt * 64 + c16 * 8;
                dst = sbase + SB + SWZ(r * 128 + c16 * 16);
            }
            asm volatile("cp.async.cg.shared.global [%0], [%1], 16;"
                         :: "r"(dst), "l"(gp) : "memory");
        }
    };

#pragma unroll
    for (int s = 0; s < NSTG - 1; s++) {
        load_stage(s, s);
        asm volatile("cp.async.commit_group;" ::: "memory");
    }

    float acc[MT][NP * 2][4];
#pragma unroll
    for (int mt = 0; mt < MT; mt++)
#pragma unroll
        for (int nt = 0; nt < NP * 2; nt++)
#pragma unroll
            for (int q = 0; q < 4; q++) acc[mt][nt][q] = 0.0f;

    for (int kt = 0; kt < NKT; kt++) {
        if (kt + NSTG - 1 < NKT) load_stage((kt + NSTG - 1) % NSTG, kt + NSTG - 1);
        asm volatile("cp.async.commit_group;" ::: "memory");
        asm volatile("cp.async.wait_group %0;" :: "n"(NSTG - 1) : "memory");
        __syncthreads();

        const uint32_t sbase = sb + (kt % NSTG) * STG;

#pragma unroll
        for (int ks = 0; ks < 4; ks++) {
            const int cb = ks * 32 + lhi;
            uint32_t af[MT][4];
#pragma unroll
            for (int mt = 0; mt < MT; mt++) {
                int row = wm + mt * 16 + lrow;
                ldsm_x4(af[mt], sbase + SA + row * 128 + (cb ^ ((row & 7) * 16)));
            }
#pragma unroll
            for (int np = 0; np < NP; np++) {
                int brow = wn + np * 16 + lrow;
                uint32_t bh4[4];
                ldsm_x4(bh4, sbase + SB + brow * 128 + (cb ^ ((brow & 7) * 16)));
#pragma unroll
                for (int mt = 0; mt < MT; mt++) {
                    mma_f16f32(acc[mt][np * 2 + 0], af[mt], bh4[0], bh4[2]);
                    mma_f16f32(acc[mt][np * 2 + 1], af[mt], bh4[1], bh4[3]);
                }
            }
        }
        __syncthreads();
    }

    const int er = m0 + wm + (lid >> 2);
    const int ec = n0 + wn + (lid & 3) * 2;
#pragma unroll
    for (int mt = 0; mt < MT; mt++)
#pragma unroll
        for (int nt = 0; nt < NP * 2; nt++) {
            if (H16OUT) {
                __half* Ch = (__half*)Cv;
                *(uint32_t*)(Ch + (size_t)(er + mt * 16) * N + ec + nt * 8) =
                    pack_h2(acc[mt][nt][0], acc[mt][nt][1]);
                *(uint32_t*)(Ch + (size_t)(er + mt * 16 + 8) * N + ec + nt * 8) =
                    pack_h2(acc[mt][nt][2], acc[mt][nt][3]);
            } else {
                float* C = (float*)Cv;
                float* c0 = C + (size_t)(er + mt * 16) * N + ec + nt * 8;
                *(float2*)c0 = make_float2(acc[mt][nt][0], acc[mt][nt][1]);
                float* c1 = c0 + 8 * N;
                *(float2*)c1 = make_float2(acc[mt][nt][2], acc[mt][nt][3]);
            }
        }
}

#define GEMM1_SMEM (4 * (128 * 128 + 192 * 128))   // 163840
#define GEMM2_SMEM (4 * (64 * 128 + 128 * 128))    // 98304

// ---------------------------------------------------------------------------
// Fused qk RMSNorm + RoPE on fp16 QKV: Q,K -> single fp16 planes.
// Q scaled by log2e/sqrt(HD).
// ---------------------------------------------------------------------------
__global__ void __launch_bounds__(256) normrope_kernel(
    const __half* __restrict__ qkvh,
    const float* __restrict__ nw_q, const float* __restrict__ nw_k,
    __half* __restrict__ qh, __half* __restrict__ kh)
{
    __shared__ float buf[HID];
    __shared__ float warpred[8];

    const int row = blockIdx.x;
    const int s = row & (S_ - 1);
    const int tid = threadIdx.x;

#pragma unroll
    for (int part = 0; part < 2; part++) {
        const __half* src = qkvh + (size_t)row * QKV_W + part * HID;
        const float* w = (part == 0) ? nw_q : nw_k;
        __half* dst = (part == 0) ? qh : kh;

        float ss = 0.0f;
        {
            uint4 v = *(const uint4*)(src + tid * 8);
            const __half2* hp = (const __half2*)&v;
#pragma unroll
            for (int q = 0; q < 4; q++) {
                float2 f = __half22float2(hp[q]);
                buf[tid * 8 + q * 2]     = f.x;
                buf[tid * 8 + q * 2 + 1] = f.y;
                ss += f.x * f.x + f.y * f.y;
            }
        }
#pragma unroll
        for (int o = 16; o; o >>= 1) ss += __shfl_xor_sync(0xffffffffu, ss, o);
        if ((tid & 31) == 0) warpred[tid >> 5] = ss;
        __syncthreads();
        float tot = 0.0f;
#pragma unroll
        for (int wi = 0; wi < 8; wi++) tot += warpred[wi];
        float rn = rsqrtf(tot * (1.0f / (float)HID) + EPS);
        if (part == 0) rn *= SCALE * LOG2E;

#pragma unroll
        for (int u = 0; u < 4; u++) {
            int p = tid + u * 256;
            int hh = p >> 6;
            int j = p & 63;
            int i1 = hh * HD + j;
            int i2 = i1 + HALF;
            float x1 = buf[i1] * rn * w[i1];
            float x2 = buf[i2] * rn * w[i2];
            float cs = g_cos[s * HALF + j];
            float sn = g_sin[s * HALF + j];
            size_t base = (size_t)row * HID;
            dst[base + i1] = __float2half_rn(x1 * cs - x2 * sn);
            dst[base + i2] = __float2half_rn(x2 * cs + x1 * sn);
        }
        __syncthreads();
    }
}

// ---------------------------------------------------------------------------
// Flash attention, fp16 mma.sync: QK 1-term, PV 1-term, base-2 softmax.
// V staged from fp16 QKV rows; PV B-frags via ldmatrix.trans.
// 64 q rows x (b,h), 128 threads / 4 warps, 2-stage KV.
// smem 80KB -> 2 CTAs/SM. (R15 shape — the 3-stage/112KB variant dropped
// occupancy to 1 CTA/SM and regressed.)
// ---------------------------------------------------------------------------
#define SQ 0
#define KVSTG 32768
#define SK(s) (16384 + (s) * KVSTG)
#define SV(s) (SK(s) + 16384)
#define ATTN_SMEM (16384 + 2 * KVSTG)   // 81920

__global__ void __launch_bounds__(128) attn_mma(
    const __half* __restrict__ qh, const __half* __restrict__ kh,
    const __half* __restrict__ qkvh, __half* __restrict__ ohi)
{
    extern __shared__ char smem[];
    const uint32_t sb = smem_u32(smem);
    const int tid = threadIdx.x;
    const int wid = tid >> 5, lid = tid & 31;
    const int lrow = lid & 15;
    const int lhi = (lid >> 4) * 16;
    const int bh = blockIdx.y;
    const int b = bh >> 4, h = bh & 15;
    const int qt = gridDim.x - 1 - blockIdx.x;   // heavy tiles first
    const int q0 = qt * 64;
    const int nkb = qt + 1;
    const int wm = wid * 16;

    // trans-load lane geometry for V fragments
    const int vm = lid >> 3;
    const int vrow_l = (vm & 1) * 8 + (lid & 7);
    const int vcol_l = (vm >> 1) * 8;

    // ---- load Q (64 rows, single plane): 1024 16B-chunks ----
#pragma unroll
    for (int u = 0; u < 8; u++) {
        int c = tid + u * 128;
        int r = c >> 4, ch = c & 15;
        int p = ch >> 3, c8 = ch & 7;
        const __half* src = qh + ((size_t)(b * 2048 + q0 + r) * HID + h * HD + ch * 8);
        uint32_t dst = sb + SQ + p * 8192 + SWZ(r * 128 + c8 * 16);
        asm volatile("cp.async.cg.shared.global [%0], [%1], 16;"
                     :: "r"(dst), "l"(src) : "memory");
    }
    asm volatile("cp.async.commit_group;" ::: "memory");

// 2048 16B-chunks per stage: K (1024 from kh) + V (1024 from qkvh rows)
#define LOAD_KV(s, kt) do {                                                    \
    int k0 = (kt) * 64;                                                        \
    _Pragma("unroll")                                                          \
    for (int u = 0; u < 16; u++) {                                             \
        int c = tid + u * 128;                                                 \
        if (c < 1024) {                                                        \
            int r = c >> 4, ch = c & 15;                                       \
            int p = ch >> 3, c8 = ch & 7;                                      \
            const __half* src = kh +                                           \
                ((size_t)(b * 2048 + k0 + r) * HID + h * HD + ch * 8);         \
            uint32_t dst = sb + SK(s) + p * 8192 + SWZ(r * 128 + c8 * 16);     \
            asm volatile("cp.async.cg.shared.global [%0], [%1], 16;"           \
                         :: "r"(dst), "l"(src) : "memory");                    \
        } else {                                                               \
            int cc = c - 1024;                                                 \
            int r = cc >> 4, ch = cc & 15;                                     \
            int p = ch >> 3, c8 = ch & 7;                                      \
            const __half* src = qkvh +                                         \
                ((size_t)(b * 2048 + k0 + r) * QKV_W + 2 * HID + h * HD + ch * 8); \
            uint32_t dst = sb + SV(s) + p * 8192 + SWZ(r * 128 + c8 * 16);     \
            asm volatile("cp.async.cg.shared.global [%0], [%1], 16;"           \
                         :: "r"(dst), "l"(src) : "memory");                    \
        }                                                                      \
    }                                                                          \
} while (0)

    LOAD_KV(0, 0);
    asm volatile("cp.async.commit_group;" ::: "memory");

    // ---- hoist Q fragments into registers ----
    asm volatile("cp.async.wait_group 1;" ::: "memory");
    __syncthreads();
    uint32_t qr[8][4];
#pragma unroll
    for (int kk = 0; kk < 8; kk++) {
        int p = kk >> 2;
        int cb = (kk & 3) * 32 + lhi;
        int arow = wm + lrow;
        ldsm_x4(qr[kk], sb + SQ + p * 8192 + arow * 128 + (cb ^ ((arow & 7) * 16)));
    }

    float accO[16][4];
#pragma unroll
    for (int nt = 0; nt < 16; nt++)
#pragma unroll
        for (int q = 0; q < 4; q++) accO[nt][q] = 0.0f;
    float m0v = -1e30f, m1v = -1e30f, l0v = 0.0f, l1v = 0.0f;

    const int grow0 = q0 + wm + (lid >> 2);
    const int grow1 = grow0 + 8;

    for (int kt = 0; kt < nkb; kt++) {
        __syncthreads();
        if (kt + 1 < nkb) LOAD_KV((kt + 1) & 1, kt + 1);
        asm volatile("cp.async.commit_group;" ::: "memory");
        asm volatile("cp.async.wait_group 1;" ::: "memory");
        __syncthreads();

        // fully-masked ktile for this warp?
        if (kt * 64 > q0 + wm + 15) continue;

        const int s = kt & 1;

        // ---- S = Q*K  (logits in log2 units) ----
        float sa[8][4];
#pragma unroll
        for (int nt = 0; nt < 8; nt++)
#pragma unroll
            for (int q = 0; q < 4; q++) sa[nt][q] = 0.0f;

#pragma unroll
        for (int kk = 0; kk < 8; kk++) {
            int p = kk >> 2;
            int cb = (kk & 3) * 32 + lhi;
#pragma unroll
            for (int np = 0; np < 4; np++) {
                int brow = np * 16 + lrow;
                uint32_t boff = p * 8192 + brow * 128 + (cb ^ ((brow & 7) * 16));
                uint32_t khf[4];
                ldsm_x4(khf, sb + SK(s) + boff);
                mma_f16f32(sa[np * 2 + 0], qr[kk], khf[0], khf[2]);
                mma_f16f32(sa[np * 2 + 1], qr[kk], khf[1], khf[3]);
            }
        }

        // ---- causal mask ----
        if ((kt + 1) * 64 - 1 > q0 + wm) {
            const int colb = kt * 64 + (lid & 3) * 2;
#pragma unroll
            for (int nt = 0; nt < 8; nt++) {
                int col = colb + nt * 8;
                if (col > grow0)     sa[nt][0] = -1e30f;
                if (col + 1 > grow0) sa[nt][1] = -1e30f;
                if (col > grow1)     sa[nt][2] = -1e30f;
                if (col + 1 > grow1) sa[nt][3] = -1e30f;
            }
        }

        // ---- online softmax (base 2) ----
        float mx0 = m0v, mx1 = m1v;
#pragma unroll
        for (int nt = 0; nt < 8; nt++) {
            mx0 = fmaxf(mx0, fmaxf(sa[nt][0], sa[nt][1]));
            mx1 = fmaxf(mx1, fmaxf(sa[nt][2], sa[nt][3]));
        }
        mx0 = fmaxf(mx0, __shfl_xor_sync(0xffffffffu, mx0, 1));
        mx0 = fmaxf(mx0, __shfl_xor_sync(0xffffffffu, mx0, 2));
        mx1 = fmaxf(mx1, __shfl_xor_sync(0xffffffffu, mx1, 1));
        mx1 = fmaxf(mx1, __shfl_xor_sync(0xffffffffu, mx1, 2));
        float alpha0 = exp2f(m0v - mx0);
        float alpha1 = exp2f(m1v - mx1);
        m0v = mx0; m1v = mx1;

        float ls0 = 0.0f, ls1 = 0.0f;
#pragma unroll
        for (int nt = 0; nt < 8; nt++) {
            sa[nt][0] = exp2f(sa[nt][0] - mx0);
            sa[nt][1] = exp2f(sa[nt][1] - mx0);
            sa[nt][2] = exp2f(sa[nt][2] - mx1);
            sa[nt][3] = exp2f(sa[nt][3] - mx1);
            ls0 += sa[nt][0] + sa[nt][1];
            ls1 += sa[nt][2] + sa[nt][3];
        }
        ls0 += __shfl_xor_sync(0xffffffffu, ls0, 1);
        ls0 += __shfl_xor_sync(0xffffffffu, ls0, 2);
        ls1 += __shfl_xor_sync(0xffffffffu, ls1, 1);
        ls1 += __shfl_xor_sync(0xffffffffu, ls1, 2);
        l0v = l0v * alpha0 + ls0;
        l1v = l1v * alpha1 + ls1;

#pragma unroll
        for (int nt = 0; nt < 16; nt++) {
            accO[nt][0] *= alpha0; accO[nt][1] *= alpha0;
            accO[nt][2] *= alpha1; accO[nt][3] *= alpha1;
        }

        // ---- P -> fp16 A-fragments ----
        uint32_t phA[8], phB[8];
#pragma unroll
        for (int nt = 0; nt < 8; nt++) {
            phA[nt] = pack_h2(sa[nt][0], sa[nt][1]);
            phB[nt] = pack_h2(sa[nt][2], sa[nt][3]);
        }

        // ---- O += P*V  (V frags via ldmatrix.trans from [token][d]) ----
#pragma unroll
        for (int ki = 0; ki < 4; ki++) {
            uint32_t aH[4] = {phA[2 * ki], phB[2 * ki], phA[2 * ki + 1], phB[2 * ki + 1]};
            int token = ki * 16 + vrow_l;
#pragma unroll
            for (int np = 0; np < 8; np++) {
                int dcol = np * 16 + vcol_l;
                int p = dcol >> 6;
                int colb = (dcol & 63) * 2;
                uint32_t vhf[4];
                ldsm_x4_t(vhf, sb + SV(s) + p * 8192 + token * 128 +
                               (colb ^ ((token & 7) * 16)));
                mma_f16f32(accO[np * 2 + 0], aH, vhf[0], vhf[1]);
                mma_f16f32(accO[np * 2 + 1], aH, vhf[2], vhf[3]);
            }
        }
    }

    // ---- epilogue: O/l -> single fp16 plane ----
    float inv0 = 1.0f / l0v, inv1 = 1.0f / l1v;
#pragma unroll
    for (int nt = 0; nt < 16; nt++) {
        int col = h * HD + nt * 8 + (lid & 3) * 2;
        size_t r0 = (size_t)(b * 2048 + grow0) * HID + col;
        size_t r1 = (size_t)(b * 2048 + grow1) * HID + col;
        *(uint32_t*)(ohi + r0) = pack_h2(accO[nt][0] * inv0, accO[nt][1] * inv0);
        *(uint32_t*)(ohi + r1) = pack_h2(accO[nt][2] * inv1, accO[nt][3] * inv1);
    }
#undef LOAD_KV
}

// ---------------------------------------------------------------------------
// launch
// ---------------------------------------------------------------------------
extern "C" void kernel_launch(void* const* d_in, const int* in_sizes, int n_in,
                              void* d_out, int out_size)
{
    const float* x     = (const float*)d_in[0];
    const float* w_in  = (const float*)d_in[1];
    const float* w_out = (const float*)d_in[2];
    const float* qnw   = (const float*)d_in[3];
    const float* knw   = (const float*)d_in[4];
    float* out = (float*)d_out;

    __half *qkvh, *ah, *b1, *b2, *qh, *kh;
    cudaGetSymbolAddress((void**)&qkvh, g_qkvh);
    cudaGetSymbolAddress((void**)&ah, g_a_hi);
    cudaGetSymbolAddress((void**)&b1, g_b1);
    cudaGetSymbolAddress((void**)&b2, g_b2);
    cudaGetSymbolAddress((void**)&qh, g_q_hi);
    cudaGetSymbolAddress((void**)&kh, g_k_hi);

    cudaFuncSetAttribute(gemm_t<2, 3, 4, true>, cudaFuncAttributeMaxDynamicSharedMemorySize, GEMM1_SMEM);
    cudaFuncSetAttribute(gemm_t<1, 2, 4, false>, cudaFuncAttributeMaxDynamicSharedMemorySize, GEMM2_SMEM);
    cudaFuncSetAttribute(attn_mma, cudaFuncAttributeMaxDynamicSharedMemorySize, ATTN_SMEM);

    // 1. one pass: x -> a plane, w_in -> b1, w_out -> b2 (fp16); rope table
    tohalf3_kernel<<<(N1F4 + N2F4 + N3F4 + 255) / 256, 256>>>(x, ah, w_in, b1, w_out, b2);
    rope_table_kernel<<<(S_ * HALF + 255) / 256, 256>>>();

    // 2. QKV = x @ w_in^T -> fp16 (128x192 tiles, 1024 CTAs)
    gemm_t<2, 3, 4, true><<<(ROWS / 128) * (QKV_W / 192), 512, GEMM1_SMEM>>>(
        ah, b1, qkvh, ROWS, QKV_W, ROWS / 128);

    // 3. norm/rope on fp16 QKV (Q pre-scaled by log2e)
    normrope_kernel<<<ROWS, 256>>>(qkvh, qnw, knw, qh, kh);

    // 4. attention (R15 2-stage shape, 2 CTAs/SM) -> fp16 O plane in ah
    attn_mma<<<dim3(S_ / 64, B_ * NH), 128, ATTN_SMEM>>>(qh, kh, qkvh, ah);

    // 5. out = O @ w_out^T (fp32 out)
    gemm_t<1, 2, 4, false><<<(ROWS / 64) * (HID / 128), 512, GEMM2_SMEM>>>(
        ah, b2, out, ROWS, HID, ROWS / 64);
}